// round 9
// baseline (speedup 1.0000x reference)
#include <cuda_runtime.h>
#include <cstdint>

// R7: mean computed as dot(enc_row, c) with c[f] = sum of w[n] over pref[n]==f,
// built once per launch by a small histogram kernel. The per-row critical path
// to `sub` is now a coalesced conflict-free LDS dot; the random gather fuses
// scale+sub+relu+store and streams with no trailing barrier.

#define THREADS 512
#define MAXCHUNK 8   // N/4/THREADS = 16384/4/512
#define STAGES 3
#define MAXF 32768

__device__ unsigned g_ticket;
__device__ float g_c[MAXF];

__global__ void build_c_kernel(const float* __restrict__ w,
                               const int* __restrict__ pref,
                               int N, int F, int fmask)
{
    extern __shared__ float sc[];
    const int tid = threadIdx.x;
    if (tid == 0) g_ticket = 0u;
    for (int i = tid; i < F; i += blockDim.x) sc[i] = 0.0f;
    __syncthreads();
    for (int i = tid; i < N; i += blockDim.x) {
        int f = fmask ? (pref[i] & fmask) : (int)((unsigned)pref[i] % (unsigned)F);
        atomicAdd(&sc[f], w[i]);
    }
    __syncthreads();
    for (int i = tid; i < F; i += blockDim.x) g_c[i] = sc[i];
}

__global__ __launch_bounds__(THREADS, 1)
void sensory_persistent7(const float* __restrict__ enc,
                         const float* __restrict__ w,
                         const int*   __restrict__ pref,
                         float* __restrict__ out,
                         int B, int N, int F, int fmask)
{
    extern __shared__ __align__(128) unsigned char smem_dyn[];
    __shared__ __align__(8) unsigned long long mbar[STAGES];
    __shared__ float warpsums[THREADS / 32];
    __shared__ int rowids_sm[STAGES];

    const int tid = threadIdx.x;
    const unsigned rowbytes = (unsigned)F * 4u;

    uint32_t b_bar[STAGES], b_buf[STAGES];
    #pragma unroll
    for (int s = 0; s < STAGES; ++s) {
        b_bar[s] = (uint32_t)__cvta_generic_to_shared(&mbar[s]);
        b_buf[s] = (uint32_t)__cvta_generic_to_shared(smem_dyn + (size_t)s * rowbytes);
    }

    if (tid == 0) {
        #pragma unroll
        for (int s = 0; s < STAGES; ++s)
            asm volatile("mbarrier.init.shared::cta.b64 [%0], 1;" :: "r"(b_bar[s]) : "memory");
        asm volatile("fence.proxy.async.shared::cta;" ::: "memory");
    }
    __syncthreads();

    // ---- preload prefs (byte offsets), weights, and c chunk into registers ----
    const int n4 = N >> 2;
    int4   poff[MAXCHUNK];
    float4 wv[MAXCHUNK];
    float4 cv[MAXCHUNK];
    {
        const int4*   pref4 = (const int4*)pref;
        const float4* w4    = (const float4*)w;
        const float4* c4    = (const float4*)g_c;
        #pragma unroll
        for (int k = 0; k < MAXCHUNK; ++k) {
            int i4 = tid + k * THREADS;
            if (i4 < n4) {
                int4 p = pref4[i4];
                if (fmask) {
                    p.x = (p.x & fmask) << 2;
                    p.y = (p.y & fmask) << 2;
                    p.z = (p.z & fmask) << 2;
                    p.w = (p.w & fmask) << 2;
                } else {
                    p.x = (int)((unsigned)p.x % (unsigned)F) << 2;
                    p.y = (int)((unsigned)p.y % (unsigned)F) << 2;
                    p.z = (int)((unsigned)p.z % (unsigned)F) << 2;
                    p.w = (int)((unsigned)p.w % (unsigned)F) << 2;
                }
                poff[k] = p;
                wv[k]   = w4[i4];
            }
            // c chunk indexed over F/4 float4s; F == N here (16384) but guard anyway
            int c_i4 = tid + k * THREADS;
            cv[k] = (c_i4 < (F >> 2)) ? c4[c_i4] : make_float4(0.f, 0.f, 0.f, 0.f);
        }
    }

    // ---- prologue: claim and issue first two rows ----
    if (tid == 0) {
        #pragma unroll
        for (int s = 0; s < 2; ++s) {
            int r = (int)atomicAdd(&g_ticket, 1u);
            rowids_sm[s] = r;
            if (r < B) {
                asm volatile("mbarrier.arrive.expect_tx.shared::cta.b64 _, [%0], %1;"
                             :: "r"(b_bar[s]), "r"(rowbytes) : "memory");
                asm volatile("cp.async.bulk.shared::cta.global.mbarrier::complete_tx::bytes "
                             "[%0], [%1], %2, [%3];"
                             :: "r"(b_buf[s]), "l"(enc + (size_t)r * (size_t)F),
                                "r"(rowbytes), "r"(b_bar[s]) : "memory");
            }
        }
    }
    __syncthreads();

    int cur = 0, nxt2 = 2;   // nxt2 = (cur + 2) % STAGES
    int par = 0;

    for (;;) {
        const int r = rowids_sm[cur];
        if (r >= B) break;

        // ---- wait for current buffer ----
        {
            const uint32_t mb = b_bar[cur];
            uint32_t done;
            asm volatile("{ .reg .pred p; "
                         "mbarrier.try_wait.parity.acquire.cta.shared::cta.b64 p, [%1], %2; "
                         "selp.b32 %0, 1, 0, p; }"
                         : "=r"(done) : "r"(mb), "r"((uint32_t)par) : "memory");
            if (!done) {
                asm volatile("{ .reg .pred P1; "
                             "WL%=: mbarrier.try_wait.parity.acquire.cta.shared::cta.b64 P1, [%0], %1, 0x989680; "
                             "@P1 bra.uni WD%=; bra.uni WL%=; WD%=: }"
                             :: "r"(mb), "r"((uint32_t)par) : "memory");
            }
        }

        const char* srow = (const char*)smem_dyn + (size_t)cur * rowbytes;

        // ---- coalesced dot pass: lsum = dot(enc_row_chunk, c_chunk) ----
        float lsum = 0.0f;
        {
            const float4* s4 = (const float4*)srow;
            #pragma unroll
            for (int k = 0; k < MAXCHUNK; ++k) {
                float4 e = s4[tid + k * THREADS];
                lsum += e.x * cv[k].x + e.y * cv[k].y + e.z * cv[k].z + e.w * cv[k].w;
            }
        }

        // ---- warp partial sums + barrier1 ----
        #pragma unroll
        for (int off = 16; off > 0; off >>= 1)
            lsum += __shfl_down_sync(0xFFFFFFFFu, lsum, off);
        if ((tid & 31) == 0) warpsums[tid >> 5] = lsum;
        __syncthreads();   // barrier1: sums visible; also all threads finished
                           // the PREVIOUS iteration's gather of buffer nxt2

        // ---- claim + issue refill TMA (buffer nxt2 is free as of barrier1) ----
        if (tid == 0) {
            int r2 = (int)atomicAdd(&g_ticket, 1u);
            rowids_sm[nxt2] = r2;
            if (r2 < B) {
                asm volatile("mbarrier.arrive.expect_tx.shared::cta.b64 _, [%0], %1;"
                             :: "r"(b_bar[nxt2]), "r"(rowbytes) : "memory");
                asm volatile("cp.async.bulk.shared::cta.global.mbarrier::complete_tx::bytes "
                             "[%0], [%1], %2, [%3];"
                             :: "r"(b_buf[nxt2]), "l"(enc + (size_t)r2 * (size_t)F),
                                "r"(rowbytes), "r"(b_bar[nxt2]) : "memory");
            }
        }

        // ---- redundant per-thread final reduce ----
        float tot = 0.0f;
        #pragma unroll
        for (int ws = 0; ws < THREADS / 32; ++ws) tot += warpsums[ws];
        const float sub = (0.1f / (float)N) * tot;

        // ---- fused gather + scale + subtract + relu + store (no trailing barrier) ----
        float4* out4 = (float4*)(out + (size_t)r * (size_t)N);
        #pragma unroll
        for (int k = 0; k < MAXCHUNK; ++k) {
            int i4 = tid + k * THREADS;
            float4 o;
            o.x = fmaxf(*(const float*)(srow + poff[k].x) * wv[k].x - sub, 0.0f);
            o.y = fmaxf(*(const float*)(srow + poff[k].y) * wv[k].y - sub, 0.0f);
            o.z = fmaxf(*(const float*)(srow + poff[k].z) * wv[k].z - sub, 0.0f);
            o.w = fmaxf(*(const float*)(srow + poff[k].w) * wv[k].w - sub, 0.0f);
            __stcs(out4 + i4, o);
        }

        // advance ring
        cur  = (cur == STAGES - 1) ? 0 : cur + 1;
        nxt2 = (nxt2 == STAGES - 1) ? 0 : nxt2 + 1;
        if (cur == 0) par ^= 1;
    }
}

extern "C" void kernel_launch(void* const* d_in, const int* in_sizes, int n_in,
                              void* d_out, int out_size)
{
    const float* enc  = (const float*)d_in[0];
    const float* w    = (const float*)d_in[1];
    const int*   pref = (const int*)d_in[2];
    float*       out  = (float*)d_out;

    const int N = in_sizes[1];
    const int B = out_size / N;
    const int F = (int)((long long)in_sizes[0] / (long long)B);
    const int fmask = ((F & (F - 1)) == 0) ? (F - 1) : 0;

    int dev = 0;
    cudaGetDevice(&dev);
    int sms = 148;
    cudaDeviceGetAttribute(&sms, cudaDevAttrMultiProcessorCount, dev);
    int grid = (B < sms) ? B : sms;

    const int csmem = F * (int)sizeof(float);
    cudaFuncSetAttribute(build_c_kernel,
                         cudaFuncAttributeMaxDynamicSharedMemorySize, csmem);

    const int smem = STAGES * F * (int)sizeof(float);
    cudaFuncSetAttribute(sensory_persistent7,
                         cudaFuncAttributeMaxDynamicSharedMemorySize, smem);

    build_c_kernel<<<1, 1024, csmem>>>(w, pref, N, F, fmask);
    sensory_persistent7<<<grid, THREADS, smem>>>(enc, w, pref, out, B, N, F, fmask);
}

// round 10
// speedup vs baseline: 1.1394x; 1.1394x over previous
#include <cuda_runtime.h>
#include <cstdint>

// R10 = R6 hot loop (best: 88.1us) + self-resetting ticket counter, removing
// the serial reset-kernel graph node (~2-3us/replay).
// Persistent kernel, 3-deep TMA smem ring, 512 threads, refill TMA claimed and
// issued at TOP of each iteration, dynamic row scheduling via global ticket.

#define THREADS 512
#define MAXCHUNK 8   // N/4/THREADS = 16384/4/512
#define STAGES 3

__device__ unsigned g_ticket;   // zero-initialized at module load
__device__ unsigned g_done;     // zero-initialized at module load

__global__ __launch_bounds__(THREADS, 1)
void sensory_persistent10(const float* __restrict__ enc,
                          const float* __restrict__ w,
                          const int*   __restrict__ pref,
                          float* __restrict__ out,
                          int B, int N, int F, int fmask)
{
    extern __shared__ __align__(128) unsigned char smem_dyn[];
    __shared__ __align__(8) unsigned long long mbar[STAGES];
    __shared__ float warpsums[THREADS / 32];
    __shared__ int rowids_sm[STAGES];

    const int tid = threadIdx.x;
    const unsigned rowbytes = (unsigned)F * 4u;

    uint32_t b_bar[STAGES], b_buf[STAGES];
    #pragma unroll
    for (int s = 0; s < STAGES; ++s) {
        b_bar[s] = (uint32_t)__cvta_generic_to_shared(&mbar[s]);
        b_buf[s] = (uint32_t)__cvta_generic_to_shared(smem_dyn + (size_t)s * rowbytes);
    }

    if (tid == 0) {
        #pragma unroll
        for (int s = 0; s < STAGES; ++s)
            asm volatile("mbarrier.init.shared::cta.b64 [%0], 1;" :: "r"(b_bar[s]) : "memory");
        asm volatile("fence.proxy.async.shared::cta;" ::: "memory");
    }
    __syncthreads();

    // ---- preload prefs (byte offsets) and weights into registers ----
    const int n4 = N >> 2;
    int4   poff[MAXCHUNK];
    float4 wv[MAXCHUNK];
    {
        const int4*   pref4 = (const int4*)pref;
        const float4* w4    = (const float4*)w;
        #pragma unroll
        for (int k = 0; k < MAXCHUNK; ++k) {
            int i4 = tid + k * THREADS;
            if (i4 < n4) {
                int4 p = pref4[i4];
                if (fmask) {
                    p.x = (p.x & fmask) << 2;
                    p.y = (p.y & fmask) << 2;
                    p.z = (p.z & fmask) << 2;
                    p.w = (p.w & fmask) << 2;
                } else {
                    p.x = (int)((unsigned)p.x % (unsigned)F) << 2;
                    p.y = (int)((unsigned)p.y % (unsigned)F) << 2;
                    p.z = (int)((unsigned)p.z % (unsigned)F) << 2;
                    p.w = (int)((unsigned)p.w % (unsigned)F) << 2;
                }
                poff[k] = p;
                wv[k]   = w4[i4];
            }
        }
    }

    // ---- prologue: claim and issue first two rows ----
    if (tid == 0) {
        #pragma unroll
        for (int s = 0; s < 2; ++s) {
            int r = (int)atomicAdd(&g_ticket, 1u);
            rowids_sm[s] = r;
            if (r < B) {
                asm volatile("mbarrier.arrive.expect_tx.shared::cta.b64 _, [%0], %1;"
                             :: "r"(b_bar[s]), "r"(rowbytes) : "memory");
                asm volatile("cp.async.bulk.shared::cta.global.mbarrier::complete_tx::bytes "
                             "[%0], [%1], %2, [%3];"
                             :: "r"(b_buf[s]), "l"(enc + (size_t)r * (size_t)F),
                                "r"(rowbytes), "r"(b_bar[s]) : "memory");
            }
        }
    }
    __syncthreads();

    int cur = 0, nxt2 = 2;   // nxt2 = (cur + 2) % STAGES
    int par = 0;

    for (;;) {
        const int r = rowids_sm[cur];   // claimed 2 iterations ago (or prologue)
        if (r >= B) break;

        // ---- claim + issue refill TMA at TOP of iteration.
        // Buffer nxt2 was fully consumed before the PREVIOUS iteration's
        // __syncthreads (gather reads precede that barrier in all threads),
        // so it is free now; issuing here maximizes TMA lead time.
        if (tid == 0) {
            int r2 = (int)atomicAdd(&g_ticket, 1u);
            rowids_sm[nxt2] = r2;
            if (r2 < B) {
                asm volatile("mbarrier.arrive.expect_tx.shared::cta.b64 _, [%0], %1;"
                             :: "r"(b_bar[nxt2]), "r"(rowbytes) : "memory");
                asm volatile("cp.async.bulk.shared::cta.global.mbarrier::complete_tx::bytes "
                             "[%0], [%1], %2, [%3];"
                             :: "r"(b_buf[nxt2]), "l"(enc + (size_t)r2 * (size_t)F),
                                "r"(rowbytes), "r"(b_bar[nxt2]) : "memory");
            }
        }

        // ---- wait for current buffer ----
        {
            const uint32_t mb = b_bar[cur];
            uint32_t done;
            asm volatile("{ .reg .pred p; "
                         "mbarrier.try_wait.parity.acquire.cta.shared::cta.b64 p, [%1], %2; "
                         "selp.b32 %0, 1, 0, p; }"
                         : "=r"(done) : "r"(mb), "r"((uint32_t)par) : "memory");
            if (!done) {
                asm volatile("{ .reg .pred P1; "
                             "WL%=: mbarrier.try_wait.parity.acquire.cta.shared::cta.b64 P1, [%0], %1, 0x989680; "
                             "@P1 bra.uni WD%=; bra.uni WL%=; WD%=: }"
                             :: "r"(mb), "r"((uint32_t)par) : "memory");
            }
        }

        const char* srow = (const char*)smem_dyn + (size_t)cur * rowbytes;

        // ---- gather into registers + local sum ----
        float lsum = 0.0f;
        float4 vals[MAXCHUNK];
        #pragma unroll
        for (int k = 0; k < MAXCHUNK; ++k) {
            float4 v;
            v.x = *(const float*)(srow + poff[k].x) * wv[k].x;
            v.y = *(const float*)(srow + poff[k].y) * wv[k].y;
            v.z = *(const float*)(srow + poff[k].z) * wv[k].z;
            v.w = *(const float*)(srow + poff[k].w) * wv[k].w;
            vals[k] = v;
            lsum += (v.x + v.y) + (v.z + v.w);
        }

        // ---- warp partial sums ----
        #pragma unroll
        for (int off = 16; off > 0; off >>= 1)
            lsum += __shfl_down_sync(0xFFFFFFFFu, lsum, off);
        if ((tid & 31) == 0) warpsums[tid >> 5] = lsum;
        __syncthreads();   // sums visible AND all reads of srow complete -> buffer release point

        // ---- redundant per-thread final reduce (no second barrier) ----
        float tot = 0.0f;
        #pragma unroll
        for (int ws = 0; ws < THREADS / 32; ++ws) tot += warpsums[ws];
        const float sub = (0.1f / (float)N) * tot;

        // ---- epilogue: subtract + relu, streaming float4 stores ----
        float4* out4 = (float4*)(out + (size_t)r * (size_t)N);
        #pragma unroll
        for (int k = 0; k < MAXCHUNK; ++k) {
            int i4 = tid + k * THREADS;
            float4 v = vals[k];
            float4 o;
            o.x = fmaxf(v.x - sub, 0.0f);
            o.y = fmaxf(v.y - sub, 0.0f);
            o.z = fmaxf(v.z - sub, 0.0f);
            o.w = fmaxf(v.w - sub, 0.0f);
            __stcs(out4 + i4, o);
        }

        // advance ring
        cur  = (cur == STAGES - 1) ? 0 : cur + 1;
        nxt2 = (nxt2 == STAGES - 1) ? 0 : nxt2 + 1;
        if (cur == 0) par ^= 1;
    }

    // ---- self-reset for the next (graph-replayed) launch ----
    // A CTA makes no further ticket claims after its loop exits, so the last
    // CTA to arrive here can safely reset the counters for the next replay.
    if (tid == 0) {
        __threadfence();
        unsigned d = atomicAdd(&g_done, 1u);
        if (d == gridDim.x - 1u) {
            g_ticket = 0u;
            g_done   = 0u;
            __threadfence();
        }
    }
}

extern "C" void kernel_launch(void* const* d_in, const int* in_sizes, int n_in,
                              void* d_out, int out_size)
{
    const float* enc  = (const float*)d_in[0];
    const float* w    = (const float*)d_in[1];
    const int*   pref = (const int*)d_in[2];
    float*       out  = (float*)d_out;

    const int N = in_sizes[1];
    const int B = out_size / N;
    const int F = (int)((long long)in_sizes[0] / (long long)B);
    const int fmask = ((F & (F - 1)) == 0) ? (F - 1) : 0;

    int dev = 0;
    cudaGetDevice(&dev);
    int sms = 148;
    cudaDeviceGetAttribute(&sms, cudaDevAttrMultiProcessorCount, dev);
    int grid = (B < sms) ? B : sms;

    const int smem = STAGES * F * (int)sizeof(float);
    cudaFuncSetAttribute(sensory_persistent10,
                         cudaFuncAttributeMaxDynamicSharedMemorySize, smem);

    sensory_persistent10<<<grid, THREADS, smem>>>(enc, w, pref, out, B, N, F, fmask);
}

// round 11
// speedup vs baseline: 1.1891x; 1.0436x over previous
#include <cuda_runtime.h>
#include <cstdint>

// R11 = R5's 1024-thread shape (best in-kernel dur) + R6/R10's dynamic ticket
// scheduling, hoisted refill TMA, and self-resetting counters (best wall
// behavior). TMA reads split 2x32KB per slot for finer DRAM interleaving.

#define THREADS 1024
#define MAXCHUNK 4   // N/4/THREADS = 16384/4/1024
#define STAGES 3

__device__ unsigned g_ticket;   // zero-initialized at module load
__device__ unsigned g_done;

__global__ __launch_bounds__(THREADS, 1)
void sensory_persistent11(const float* __restrict__ enc,
                          const float* __restrict__ w,
                          const int*   __restrict__ pref,
                          float* __restrict__ out,
                          int B, int N, int F, int fmask)
{
    extern __shared__ __align__(128) unsigned char smem_dyn[];
    __shared__ __align__(8) unsigned long long mbar[STAGES];
    __shared__ float warpsums[THREADS / 32];
    __shared__ int rowids_sm[STAGES];

    const int tid = threadIdx.x;
    const unsigned rowbytes = (unsigned)F * 4u;
    const unsigned halfbytes = rowbytes >> 1;

    const uint32_t buf_base = (uint32_t)__cvta_generic_to_shared(smem_dyn);
    const uint32_t bar_base = (uint32_t)__cvta_generic_to_shared(&mbar[0]);

    if (tid == 0) {
        #pragma unroll
        for (int s = 0; s < STAGES; ++s)
            asm volatile("mbarrier.init.shared::cta.b64 [%0], 1;"
                         :: "r"(bar_base + 8u * s) : "memory");
        asm volatile("fence.proxy.async.shared::cta;" ::: "memory");
    }
    __syncthreads();

    // ---- preload prefs as packed 2x16-bit byte offsets + weights ----
    const int n4 = N >> 2;
    uint32_t plo[MAXCHUNK], phi[MAXCHUNK];   // (x | y<<16), (z | w<<16)
    float4 wv[MAXCHUNK];
    {
        const int4*   pref4 = (const int4*)pref;
        const float4* w4    = (const float4*)w;
        #pragma unroll
        for (int k = 0; k < MAXCHUNK; ++k) {
            int i4 = tid + k * THREADS;
            if (i4 < n4) {
                int4 p = pref4[i4];
                uint32_t ox, oy, oz, ow;
                if (fmask) {
                    ox = (uint32_t)(p.x & fmask) << 2;
                    oy = (uint32_t)(p.y & fmask) << 2;
                    oz = (uint32_t)(p.z & fmask) << 2;
                    ow = (uint32_t)(p.w & fmask) << 2;
                } else {
                    ox = ((unsigned)p.x % (unsigned)F) << 2;
                    oy = ((unsigned)p.y % (unsigned)F) << 2;
                    oz = ((unsigned)p.z % (unsigned)F) << 2;
                    ow = ((unsigned)p.w % (unsigned)F) << 2;
                }
                plo[k] = ox | (oy << 16);
                phi[k] = oz | (ow << 16);
                wv[k]  = w4[i4];
            } else {
                plo[k] = phi[k] = 0;
                wv[k] = make_float4(0.f, 0.f, 0.f, 0.f);
            }
        }
    }

    // ---- prologue: claim and issue first two rows (2x32KB copies each) ----
    if (tid == 0) {
        #pragma unroll
        for (int s = 0; s < 2; ++s) {
            int r = (int)atomicAdd(&g_ticket, 1u);
            rowids_sm[s] = r;
            if (r < B) {
                const uint32_t mb = bar_base + 8u * s;
                const uint32_t bf = buf_base + s * rowbytes;
                const char* src = (const char*)(enc + (size_t)r * (size_t)F);
                asm volatile("mbarrier.arrive.expect_tx.shared::cta.b64 _, [%0], %1;"
                             :: "r"(mb), "r"(rowbytes) : "memory");
                asm volatile("cp.async.bulk.shared::cta.global.mbarrier::complete_tx::bytes "
                             "[%0], [%1], %2, [%3];"
                             :: "r"(bf), "l"(src), "r"(halfbytes), "r"(mb) : "memory");
                asm volatile("cp.async.bulk.shared::cta.global.mbarrier::complete_tx::bytes "
                             "[%0], [%1], %2, [%3];"
                             :: "r"(bf + halfbytes), "l"(src + halfbytes),
                                "r"(halfbytes), "r"(mb) : "memory");
            }
        }
    }
    __syncthreads();

    int cur = 0, nxt2 = 2;   // nxt2 = (cur + 2) % STAGES
    int par = 0;

    for (;;) {
        const int r = rowids_sm[cur];   // claimed 2 iterations ago (or prologue)
        if (r >= B) break;

        // ---- claim + issue refill TMA at TOP of iteration.
        // Buffer nxt2's gather reads all preceded the PREVIOUS iteration's
        // __syncthreads, so it is free now; issuing here maximizes lead time.
        if (tid == 0) {
            int r2 = (int)atomicAdd(&g_ticket, 1u);
            rowids_sm[nxt2] = r2;
            if (r2 < B) {
                const uint32_t mb = bar_base + 8u * nxt2;
                const uint32_t bf = buf_base + nxt2 * rowbytes;
                const char* src = (const char*)(enc + (size_t)r2 * (size_t)F);
                asm volatile("mbarrier.arrive.expect_tx.shared::cta.b64 _, [%0], %1;"
                             :: "r"(mb), "r"(rowbytes) : "memory");
                asm volatile("cp.async.bulk.shared::cta.global.mbarrier::complete_tx::bytes "
                             "[%0], [%1], %2, [%3];"
                             :: "r"(bf), "l"(src), "r"(halfbytes), "r"(mb) : "memory");
                asm volatile("cp.async.bulk.shared::cta.global.mbarrier::complete_tx::bytes "
                             "[%0], [%1], %2, [%3];"
                             :: "r"(bf + halfbytes), "l"(src + halfbytes),
                                "r"(halfbytes), "r"(mb) : "memory");
            }
        }

        // ---- wait for current buffer ----
        {
            const uint32_t mb = bar_base + 8u * cur;
            uint32_t done;
            asm volatile("{ .reg .pred p; "
                         "mbarrier.try_wait.parity.acquire.cta.shared::cta.b64 p, [%1], %2; "
                         "selp.b32 %0, 1, 0, p; }"
                         : "=r"(done) : "r"(mb), "r"((uint32_t)par) : "memory");
            if (!done) {
                asm volatile("{ .reg .pred P1; "
                             "WL%=: mbarrier.try_wait.parity.acquire.cta.shared::cta.b64 P1, [%0], %1, 0x989680; "
                             "@P1 bra.uni WD%=; bra.uni WL%=; WD%=: }"
                             :: "r"(mb), "r"((uint32_t)par) : "memory");
            }
        }

        const char* srow = (const char*)smem_dyn + (size_t)cur * rowbytes;

        // ---- gather into registers + local sum ----
        float lsum = 0.0f;
        float4 vals[MAXCHUNK];
        #pragma unroll
        for (int k = 0; k < MAXCHUNK; ++k) {
            float4 v;
            v.x = *(const float*)(srow + (plo[k] & 0xFFFFu)) * wv[k].x;
            v.y = *(const float*)(srow + (plo[k] >> 16))     * wv[k].y;
            v.z = *(const float*)(srow + (phi[k] & 0xFFFFu)) * wv[k].z;
            v.w = *(const float*)(srow + (phi[k] >> 16))     * wv[k].w;
            vals[k] = v;
            lsum += (v.x + v.y) + (v.z + v.w);
        }

        // ---- warp partial sums ----
        #pragma unroll
        for (int off = 16; off > 0; off >>= 1)
            lsum += __shfl_down_sync(0xFFFFFFFFu, lsum, off);
        if ((tid & 31) == 0) warpsums[tid >> 5] = lsum;
        __syncthreads();   // sums visible AND all reads of srow done -> release point

        // ---- redundant per-thread final reduce (no second barrier) ----
        float tot = 0.0f;
        #pragma unroll
        for (int ws = 0; ws < THREADS / 32; ++ws) tot += warpsums[ws];
        const float sub = (0.1f / (float)N) * tot;

        // ---- epilogue: subtract + relu, streaming float4 stores ----
        float4* out4 = (float4*)(out + (size_t)r * (size_t)N);
        #pragma unroll
        for (int k = 0; k < MAXCHUNK; ++k) {
            int i4 = tid + k * THREADS;
            float4 v = vals[k];
            float4 o;
            o.x = fmaxf(v.x - sub, 0.0f);
            o.y = fmaxf(v.y - sub, 0.0f);
            o.z = fmaxf(v.z - sub, 0.0f);
            o.w = fmaxf(v.w - sub, 0.0f);
            __stcs(out4 + i4, o);
        }

        // advance ring
        cur  = (cur == STAGES - 1) ? 0 : cur + 1;
        nxt2 = (nxt2 == STAGES - 1) ? 0 : nxt2 + 1;
        if (cur == 0) par ^= 1;
    }

    // ---- self-reset for the next (graph-replayed) launch ----
    if (tid == 0) {
        __threadfence();
        unsigned d = atomicAdd(&g_done, 1u);
        if (d == gridDim.x - 1u) {
            g_ticket = 0u;
            g_done   = 0u;
            __threadfence();
        }
    }
}

extern "C" void kernel_launch(void* const* d_in, const int* in_sizes, int n_in,
                              void* d_out, int out_size)
{
    const float* enc  = (const float*)d_in[0];
    const float* w    = (const float*)d_in[1];
    const int*   pref = (const int*)d_in[2];
    float*       out  = (float*)d_out;

    const int N = in_sizes[1];
    const int B = out_size / N;
    const int F = (int)((long long)in_sizes[0] / (long long)B);
    const int fmask = ((F & (F - 1)) == 0) ? (F - 1) : 0;

    int dev = 0;
    cudaGetDevice(&dev);
    int sms = 148;
    cudaDeviceGetAttribute(&sms, cudaDevAttrMultiProcessorCount, dev);
    int grid = (B < sms) ? B : sms;

    const int smem = STAGES * F * (int)sizeof(float);
    cudaFuncSetAttribute(sensory_persistent11,
                         cudaFuncAttributeMaxDynamicSharedMemorySize, smem);

    sensory_persistent11<<<grid, THREADS, smem>>>(enc, w, pref, out, B, N, F, fmask);
}